// round 17
// baseline (speedup 1.0000x reference)
#include <cuda_runtime.h>
#include <math.h>
#include <stdint.h>

#define B_SZ 64
#define L_SEQ 196
#define D_MODEL 192
#define DEPTH 24
#define D_INNER 384
#define D_STATE 16
#define D_CONV 4
#define DT_RANK 12
#define N_CLS 1000
#define XPROJ_N (DT_RANK + 2*D_STATE)   // 44
#define ROWS (B_SZ*L_SEQ)               // 12544
#define K_PATCH 768                      // 3*16*16

// ---------------- scratch ----------------
__device__ float g_residual[ROWS*D_MODEL];
__device__ float g_hn[ROWS*D_MODEL];
__device__ float g_xz[ROWS*2*D_INNER];
__device__ float g_xb[ROWS*D_INNER];
__device__ float g_xdbl[2*ROWS*XPROJ_N];    // two split-K halves
__device__ float g_y[ROWS*D_INNER];
__device__ float g_wpatch[D_MODEL*K_PATCH];
__device__ float g_win[DEPTH*2*D_INNER*D_MODEL];
__device__ float g_wx[DEPTH*XPROJ_N*D_INNER];
__device__ float g_wout[DEPTH*D_MODEL*D_INNER];

// ================= helpers =================
__device__ __forceinline__ uint32_t f2tf32(float f) {
    uint32_t o;
    asm("cvt.rna.tf32.f32 %0, %1;" : "=r"(o) : "f"(f));
    return o;
}
__device__ __forceinline__ float tf32r(float f) { return __uint_as_float(f2tf32(f)); }

__global__ void round_tf32_kernel(const float* __restrict__ src, float* __restrict__ dst, int n) {
    int i = blockIdx.x * blockDim.x + threadIdx.x;
    int stride = gridDim.x * blockDim.x;
    for (; i < n; i += stride) dst[i] = tf32r(src[i]);
}

__device__ __forceinline__ uint32_t smem_u32(const void* p) {
    uint32_t a;
    asm("{ .reg .u64 t; cvta.to.shared.u64 t, %1; cvt.u32.u64 %0, t; }" : "=r"(a) : "l"(p));
    return a;
}
#define CP_ASYNC(dst, src, sz) \
    asm volatile("cp.async.cg.shared.global [%0], [%1], 16, %2;" :: "r"(dst), "l"(src), "r"(sz))
#define CP_COMMIT() asm volatile("cp.async.commit_group;" ::: "memory")
#define CP_WAIT(n)  asm volatile("cp.async.wait_group %0;" :: "n"(n) : "memory")

__device__ __forceinline__ void mma1688(float* c, const uint32_t* a, const uint32_t* b) {
    asm volatile(
        "mma.sync.aligned.m16n8k8.row.col.f32.tf32.tf32.f32 "
        "{%0,%1,%2,%3}, {%4,%5,%6,%7}, {%8,%9}, {%0,%1,%2,%3};"
        : "+f"(c[0]), "+f"(c[1]), "+f"(c[2]), "+f"(c[3])
        : "r"(a[0]), "r"(a[1]), "r"(a[2]), "r"(a[3]), "r"(b[0]), "r"(b[1]));
}

#define GA_STRIDE 36

// ================= gemm_mma: BM=128, BN=64, BK=32, single-sync 2-stage =================
#define STAGE_BYTES ((128+64)*GA_STRIDE*4)   // 27648
#define SMEM_W_OFF (128*GA_STRIDE)

__global__ __launch_bounds__(256, 3) void gemm_mma(
        const float* __restrict__ A, const float* __restrict__ W,
        float* __restrict__ C, int M, int N, int K,
        const float* __restrict__ bias, int accum,
        int Kfull, size_t Cstride) {
    extern __shared__ float smem[];
    int tid = threadIdx.x;
    int wid = tid >> 5, lid = tid & 31;
    int wm = wid & 3, wn = wid >> 2;
    int group = lid >> 2, tq = lid & 3;
    int bm = blockIdx.y * 128, bn = blockIdx.x * 64;
    int kofs = blockIdx.z * K;
    C += (size_t)blockIdx.z * Cstride;
    uint32_t sb = smem_u32(smem);
    int nk = K >> 5;

    auto load_stage = [&](int st, int kc) {
        uint32_t base = sb + st * STAGE_BYTES;
        #pragma unroll
        for (int i = 0; i < 4; i++) {
            int q = tid * 4 + i;
            int row = q >> 3, quad = q & 7;
            uint32_t dst = base + (row * GA_STRIDE + quad * 4) * 4;
            const float* src = A + (size_t)(bm + row) * Kfull + kofs + (size_t)kc * 32 + quad * 4;
            CP_ASYNC(dst, src, 16);
        }
        #pragma unroll
        for (int i = 0; i < 2; i++) {
            int q = tid * 2 + i;
            int row = q >> 3, quad = q & 7;
            int n = bn + row;
            uint32_t dst = base + (SMEM_W_OFF + row * GA_STRIDE + quad * 4) * 4;
            const float* src = (n < N) ? (W + (size_t)n * Kfull + kofs + (size_t)kc * 32 + quad * 4) : W;
            CP_ASYNC(dst, src, (n < N) ? 16 : 0);
        }
        CP_COMMIT();
    };

    float acc[2][4][4] = {};
    load_stage(0, 0);
    for (int k0 = 0; k0 < nk; k0++) {
        CP_WAIT(0);
        __syncthreads();
        if (k0 + 1 < nk) load_stage((k0 + 1) & 1, k0 + 1);
        const float* sA = smem + (size_t)(k0 & 1) * (STAGE_BYTES / 4);
        const float* sW = sA + SMEM_W_OFF;
        #pragma unroll
        for (int kk = 0; kk < 32; kk += 8) {
            uint32_t a[2][4], b[4][2];
            #pragma unroll
            for (int mi = 0; mi < 2; mi++) {
                int r = wm * 32 + mi * 16 + group;
                a[mi][0] = __float_as_uint(sA[r * GA_STRIDE + kk + tq]);
                a[mi][1] = __float_as_uint(sA[(r + 8) * GA_STRIDE + kk + tq]);
                a[mi][2] = __float_as_uint(sA[r * GA_STRIDE + kk + tq + 4]);
                a[mi][3] = __float_as_uint(sA[(r + 8) * GA_STRIDE + kk + tq + 4]);
            }
            #pragma unroll
            for (int ni = 0; ni < 4; ni++) {
                int r = wn * 32 + ni * 8 + group;
                b[ni][0] = __float_as_uint(sW[r * GA_STRIDE + kk + tq]);
                b[ni][1] = __float_as_uint(sW[r * GA_STRIDE + kk + tq + 4]);
            }
            #pragma unroll
            for (int mi = 0; mi < 2; mi++)
                #pragma unroll
                for (int ni = 0; ni < 4; ni++)
                    mma1688(acc[mi][ni], a[mi], b[ni]);
        }
    }
    #pragma unroll
    for (int mi = 0; mi < 2; mi++) {
        int m0 = bm + wm * 32 + mi * 16 + group;
        #pragma unroll
        for (int ni = 0; ni < 4; ni++) {
            int n0 = bn + wn * 32 + ni * 8 + tq * 2;
            if (n0 < N) {
                float bx = 0.f, by = 0.f;
                if (bias) { bx = bias[n0]; by = bias[n0 + 1]; }
                float2 o0 = make_float2(acc[mi][ni][0] + bx, acc[mi][ni][1] + by);
                float2 o1 = make_float2(acc[mi][ni][2] + bx, acc[mi][ni][3] + by);
                float* p0 = &C[(size_t)m0 * N + n0];
                float* p1 = &C[(size_t)(m0 + 8) * N + n0];
                if (accum) {
                    float2 r0 = *(const float2*)p0;
                    float2 r1 = *(const float2*)p1;
                    o0.x = r0.x + o0.x; o0.y = r0.y + o0.y;
                    o1.x = r1.x + o1.x; o1.y = r1.y + o1.y;
                }
                *(float2*)p0 = o0;
                *(float2*)p1 = o1;
            }
        }
    }
}

// ================= gemm_wide: BM=128, BN=128, BK=32, 3-stage single-sync (in_proj) =================
#define WIDE_STAGE ((128+128)*GA_STRIDE*4)   // 36864
#define WIDE_W_OFF (128*GA_STRIDE)

__global__ __launch_bounds__(256, 2) void gemm_wide(
        const float* __restrict__ A, const float* __restrict__ W,
        float* __restrict__ C, int M, int N, int K) {
    extern __shared__ float smem[];
    int tid = threadIdx.x;
    int wid = tid >> 5, lid = tid & 31;
    int wm = wid & 3, wn = wid >> 2;
    int group = lid >> 2, tq = lid & 3;
    int bm = blockIdx.y * 128, bn = blockIdx.x * 128;
    uint32_t sb = smem_u32(smem);
    int nk = K >> 5;

    auto load_stage = [&](int st, int kc) {
        uint32_t base = sb + st * WIDE_STAGE;
        #pragma unroll
        for (int i = 0; i < 4; i++) {
            int q = tid * 4 + i;
            int row = q >> 3, quad = q & 7;
            uint32_t dst = base + (row * GA_STRIDE + quad * 4) * 4;
            const float* src = A + (size_t)(bm + row) * K + (size_t)kc * 32 + quad * 4;
            CP_ASYNC(dst, src, 16);
        }
        #pragma unroll
        for (int i = 0; i < 4; i++) {
            int q = tid * 4 + i;
            int row = q >> 3, quad = q & 7;
            int n = bn + row;
            uint32_t dst = base + (WIDE_W_OFF + row * GA_STRIDE + quad * 4) * 4;
            const float* src = (n < N) ? (W + (size_t)n * K + (size_t)kc * 32 + quad * 4) : W;
            CP_ASYNC(dst, src, (n < N) ? 16 : 0);
        }
        CP_COMMIT();
    };

    float acc[2][8][4] = {};
    load_stage(0, 0);
    load_stage(1, 1);
    for (int k0 = 0; k0 < nk; k0++) {
        if (k0 < nk - 1) CP_WAIT(1);
        else             CP_WAIT(0);
        __syncthreads();
        if (k0 + 2 < nk) load_stage((k0 + 2) % 3, k0 + 2);
        const float* sA = smem + (size_t)(k0 % 3) * (WIDE_STAGE / 4);
        const float* sW = sA + WIDE_W_OFF;
        #pragma unroll
        for (int kk = 0; kk < 32; kk += 8) {
            uint32_t a[2][4], b[8][2];
            #pragma unroll
            for (int mi = 0; mi < 2; mi++) {
                int r = wm * 32 + mi * 16 + group;
                a[mi][0] = __float_as_uint(sA[r * GA_STRIDE + kk + tq]);
                a[mi][1] = __float_as_uint(sA[(r + 8) * GA_STRIDE + kk + tq]);
                a[mi][2] = __float_as_uint(sA[r * GA_STRIDE + kk + tq + 4]);
                a[mi][3] = __float_as_uint(sA[(r + 8) * GA_STRIDE + kk + tq + 4]);
            }
            #pragma unroll
            for (int ni = 0; ni < 8; ni++) {
                int r = wn * 64 + ni * 8 + group;
                b[ni][0] = __float_as_uint(sW[r * GA_STRIDE + kk + tq]);
                b[ni][1] = __float_as_uint(sW[r * GA_STRIDE + kk + tq + 4]);
            }
            #pragma unroll
            for (int mi = 0; mi < 2; mi++)
                #pragma unroll
                for (int ni = 0; ni < 8; ni++)
                    mma1688(acc[mi][ni], a[mi], b[ni]);
        }
    }
    #pragma unroll
    for (int mi = 0; mi < 2; mi++) {
        int m0 = bm + wm * 32 + mi * 16 + group;
        #pragma unroll
        for (int ni = 0; ni < 8; ni++) {
            int n0 = bn + wn * 64 + ni * 8 + tq * 2;
            if (n0 < N) {
                *(float2*)&C[(size_t)m0 * N + n0] = make_float2(acc[mi][ni][0], acc[mi][ni][1]);
                *(float2*)&C[(size_t)(m0 + 8) * N + n0] = make_float2(acc[mi][ni][2], acc[mi][ni][3]);
            }
        }
    }
}

// ================= im2col =================
__global__ void im2col_kernel(const float* __restrict__ x, float* __restrict__ col) {
    int idx = blockIdx.x * blockDim.x + threadIdx.x;
    if (idx >= ROWS * K_PATCH) return;
    int k  = idx % K_PATCH;
    int bl = idx / K_PATCH;
    int l  = bl % L_SEQ;
    int b  = bl / L_SEQ;
    int c  = k / 256;
    int rem = k % 256;
    int i = rem / 16, j = rem % 16;
    int ph = l / 14, pw = l % 14;
    col[idx] = tf32r(x[((b*3 + c)*224 + ph*16 + i)*224 + pw*16 + j]);
}

// ================= warp-per-row pure LayerNorm: residual -> hn =================
__global__ __launch_bounds__(256) void ln_kernel(
        const float* __restrict__ residual, float* __restrict__ hn,
        const float* __restrict__ w, const float* __restrict__ b) {
    int warp = threadIdx.x >> 5, lane = threadIdx.x & 31;
    int row = blockIdx.x * 8 + warp;
    size_t base = (size_t)row * D_MODEL;
    float v[6];
    float sum = 0.f;
    #pragma unroll
    for (int j = 0; j < 6; j++) {
        v[j] = residual[base + lane + j*32];
        sum += v[j];
    }
    #pragma unroll
    for (int o = 16; o > 0; o >>= 1) sum += __shfl_xor_sync(0xffffffffu, sum, o);
    float mean = sum * (1.f/192.f);
    float sq = 0.f;
    #pragma unroll
    for (int j = 0; j < 6; j++) { float d = v[j] - mean; sq += d*d; }
    #pragma unroll
    for (int o = 16; o > 0; o >>= 1) sq += __shfl_xor_sync(0xffffffffu, sq, o);
    float rstd = rsqrtf(sq * (1.f/192.f) + 1e-5f);
    #pragma unroll
    for (int j = 0; j < 6; j++) {
        int c = lane + j*32;
        hn[base + c] = tf32r((v[j] - mean) * rstd * w[c] + b[c]);
    }
}

// ================= causal depthwise conv1d + SiLU, sliding window =================
__global__ __launch_bounds__(384) void conv_silu_kernel(
        const float* __restrict__ xz, const float* __restrict__ cw,
        const float* __restrict__ cb, float* __restrict__ xb) {
    int d = threadIdx.x;
    int b = blockIdx.x;
    int l0 = blockIdx.y * 49;
    float w0 = cw[d*D_CONV+0], w1 = cw[d*D_CONV+1], w2 = cw[d*D_CONV+2], w3 = cw[d*D_CONV+3];
    float bias = cb[d];
    size_t base = (size_t)b*L_SEQ*(2*D_INNER) + d;
    size_t obase = (size_t)b*L_SEQ*D_INNER + d;
    float xm3 = (l0 >= 3) ? xz[base + (size_t)(l0-3)*(2*D_INNER)] : 0.f;
    float xm2 = (l0 >= 2) ? xz[base + (size_t)(l0-2)*(2*D_INNER)] : 0.f;
    float xm1 = (l0 >= 1) ? xz[base + (size_t)(l0-1)*(2*D_INNER)] : 0.f;
    #pragma unroll 7
    for (int l = l0; l < l0 + 49; l++) {
        float x0 = xz[base + (size_t)l*(2*D_INNER)];
        float acc = bias + w0*xm3 + w1*xm2 + w2*xm1 + w3*x0;
        float sig = 1.f / (1.f + __expf(-acc));
        xb[obase + (size_t)l*D_INNER] = acc * sig;
        xm3 = xm2; xm2 = xm1; xm1 = x0;
    }
}

// ================= scan: 2 threads/channel, packed sdbl for LDS.128 =================
// sdbl row layout (48 floats, 192B pitch): dt[0:12), pad[12:16), B[16:32), C[32:48)
#define SCH 7
#define SROW 48
__global__ __launch_bounds__(256) void scan_kernel(
        const float* __restrict__ xb, const float* __restrict__ xdbl,
        const float* __restrict__ xz, const float* __restrict__ A_log,
        const float* __restrict__ Dskip, const float* __restrict__ dtw,
        const float* __restrict__ dtb, float* __restrict__ y) {
    int b = blockIdx.y;
    int t = threadIdx.x;
    int dl = t >> 1;
    int half = t & 1;
    int d = blockIdx.x * 128 + dl;
    __shared__ __align__(16) float sdbl[L_SEQ][SROW];
    {   // sum split-K halves and repack: col = c<12 ? c : c+4
        const float* s0 = &xdbl[(size_t)b*L_SEQ*XPROJ_N];
        const float* s1 = s0 + (size_t)ROWS*XPROJ_N;
        for (int idx = t; idx < L_SEQ*XPROJ_N; idx += 256) {
            int l = idx / XPROJ_N, c = idx % XPROJ_N;
            int col = (c < DT_RANK) ? c : c + 4;
            sdbl[l][col] = s0[idx] + s1[idx];
        }
    }
    __syncthreads();

    float wdt[DT_RANK];
    #pragma unroll
    for (int r = 0; r < DT_RANK; r++) wdt[r] = dtw[d*DT_RANK + r];
    float bdt = dtb[d];
    float a0 = -__expf(A_log[d*D_STATE]);
    float a[8], h[8];
    #pragma unroll
    for (int n = 0; n < 8; n++) {
        a[n] = -__expf(A_log[d*D_STATE + half*8 + n]);
        h[n] = 0.f;
    }
    bool structured = true;
    #pragma unroll
    for (int n = 0; n < 8; n++)
        structured = structured && (a[n] == a0*(float)(half*8 + n + 1));
    float Dd = Dskip[d];

    size_t base0 = (size_t)b*L_SEQ*D_INNER + d;
    size_t zbase0 = (size_t)b*L_SEQ*(2*D_INNER) + D_INNER + d;

    float ub[2][SCH], zb[2][SCH];
    #pragma unroll
    for (int j = 0; j < SCH; j++) {
        ub[0][j] = xb[base0 + (size_t)j*D_INNER];
        zb[0][j] = xz[zbase0 + (size_t)j*(2*D_INNER)];
    }

    int boff = 16 + half*8, coff = 32 + half*8;

    #pragma unroll 2
    for (int c = 0; c < L_SEQ/SCH; c++) {
        int cur = c & 1, nxt = cur ^ 1;
        if (c + 1 < L_SEQ/SCH) {
            int lb = (c + 1) * SCH;
            #pragma unroll
            for (int j = 0; j < SCH; j++) {
                ub[nxt][j] = xb[base0 + (size_t)(lb + j)*D_INNER];
                zb[nxt][j] = xz[zbase0 + (size_t)(lb + j)*(2*D_INNER)];
            }
        }
        #pragma unroll
        for (int j = 0; j < SCH; j++) {
            int l = c * SCH + j;
            float u = ub[cur][j], z = zb[cur][j];
            float4 s0v = *(const float4*)&sdbl[l][0];
            float4 s1v = *(const float4*)&sdbl[l][4];
            float4 s2v = *(const float4*)&sdbl[l][8];
            float dt0 = bdt, dt1 = 0.f;
            dt0 += s0v.x * wdt[0];  dt1 += s0v.y * wdt[1];
            dt0 += s0v.z * wdt[2];  dt1 += s0v.w * wdt[3];
            dt0 += s1v.x * wdt[4];  dt1 += s1v.y * wdt[5];
            dt0 += s1v.z * wdt[6];  dt1 += s1v.w * wdt[7];
            dt0 += s2v.x * wdt[8];  dt1 += s2v.y * wdt[9];
            dt0 += s2v.z * wdt[10]; dt1 += s2v.w * wdt[11];
            float dt = dt0 + dt1;
            dt = (dt > 15.f) ? dt : __logf(1.f + __expf(dt));
            float du = dt * u;
            float e[8];
            if (structured) {
                float w = __expf(dt * a0);
                float w2 = w * w;
                float w4 = w2 * w2;
                e[0] = w;        e[1] = w2;
                e[2] = w2 * w;   e[3] = w4;
                e[4] = w4 * w;   e[5] = w4 * w2;
                e[6] = w4 * e[2]; e[7] = w4 * w4;
                if (half) {
                    float w8 = e[7];
                    #pragma unroll
                    for (int n = 0; n < 8; n++) e[n] *= w8;
                }
            } else {
                #pragma unroll
                for (int n = 0; n < 8; n++) e[n] = __expf(dt * a[n]);
            }
            float4 B0 = *(const float4*)&sdbl[l][boff];
            float4 B1 = *(const float4*)&sdbl[l][boff + 4];
            float4 C0 = *(const float4*)&sdbl[l][coff];
            float4 C1 = *(const float4*)&sdbl[l][coff + 4];
            float yv0 = 0.f, yv1 = 0.f;
            h[0] = e[0]*h[0] + du*B0.x;  h[1] = e[1]*h[1] + du*B0.y;
            yv0 += h[0]*C0.x;            yv1 += h[1]*C0.y;
            h[2] = e[2]*h[2] + du*B0.z;  h[3] = e[3]*h[3] + du*B0.w;
            yv0 += h[2]*C0.z;            yv1 += h[3]*C0.w;
            h[4] = e[4]*h[4] + du*B1.x;  h[5] = e[5]*h[5] + du*B1.y;
            yv0 += h[4]*C1.x;            yv1 += h[5]*C1.y;
            h[6] = e[6]*h[6] + du*B1.z;  h[7] = e[7]*h[7] + du*B1.w;
            yv0 += h[6]*C1.z;            yv1 += h[7]*C1.w;
            float yv = yv0 + yv1;
            yv += __shfl_xor_sync(0xffffffffu, yv, 1);
            if (!half) {
                yv += u * Dd;
                float sig = 1.f / (1.f + __expf(-z));
                y[base0 + (size_t)l*D_INNER] = tf32r(yv * (z * sig));
            }
        }
    }
}

// ================= final: LN(residual last token) + head =================
__global__ void final_kernel(const float* __restrict__ residual,
                             const float* __restrict__ nw, const float* __restrict__ nb,
                             const float* __restrict__ hw, const float* __restrict__ hb,
                             float* __restrict__ out) {
    int b = blockIdx.x;
    int t = threadIdx.x;               // 256 threads
    __shared__ float sh[D_MODEL];
    __shared__ float red[8];
    int row = b*L_SEQ + (L_SEQ - 1);
    float v = 0.f;
    if (t < D_MODEL) v = residual[row*D_MODEL + t];
    float s = v;
    #pragma unroll
    for (int o = 16; o > 0; o >>= 1) s += __shfl_xor_sync(0xffffffffu, s, o);
    if ((t & 31) == 0) red[t >> 5] = s;
    __syncthreads();
    float mean = 0.f;
    #pragma unroll
    for (int i = 0; i < 8; i++) mean += red[i];
    mean *= (1.f/192.f);
    __syncthreads();
    float dv = (t < D_MODEL) ? (v - mean) : 0.f;
    s = dv*dv;
    #pragma unroll
    for (int o = 16; o > 0; o >>= 1) s += __shfl_xor_sync(0xffffffffu, s, o);
    if ((t & 31) == 0) red[t >> 5] = s;
    __syncthreads();
    float var = 0.f;
    #pragma unroll
    for (int i = 0; i < 8; i++) var += red[i];
    var *= (1.f/192.f);
    if (t < D_MODEL) sh[t] = dv * rsqrtf(var + 1e-5f) * nw[t] + nb[t];
    __syncthreads();
    for (int o = t; o < N_CLS; o += 256) {
        float acc = hb[o];
        #pragma unroll 4
        for (int k = 0; k < D_MODEL; k++) acc += sh[k] * hw[o*D_MODEL + k];
        out[b*N_CLS + o] = acc;
    }
}

extern "C" void kernel_launch(void* const* d_in, const int* in_sizes, int n_in,
                              void* d_out, int out_size) {
    const float* x        = (const float*)d_in[0];
    const float* patch_w  = (const float*)d_in[1];
    const float* patch_b  = (const float*)d_in[2];
    const float* in_w     = (const float*)d_in[3];
    const float* conv_w   = (const float*)d_in[4];
    const float* conv_b   = (const float*)d_in[5];
    const float* xproj_w  = (const float*)d_in[6];
    const float* dt_w     = (const float*)d_in[7];
    const float* dt_b     = (const float*)d_in[8];
    const float* A_log    = (const float*)d_in[9];
    const float* D_skip   = (const float*)d_in[10];
    const float* out_w    = (const float*)d_in[11];
    const float* norm_w   = (const float*)d_in[12];
    const float* norm_b   = (const float*)d_in[13];
    const float* normf_w  = (const float*)d_in[14];
    const float* normf_b  = (const float*)d_in[15];
    const float* head_w   = (const float*)d_in[16];
    const float* head_b   = (const float*)d_in[17];
    float* out = (float*)d_out;

    float *residual, *hn, *xz, *xb, *xdbl, *y;
    float *wpatch, *win, *wx, *wout;
    cudaGetSymbolAddress((void**)&residual, g_residual);
    cudaGetSymbolAddress((void**)&hn,       g_hn);
    cudaGetSymbolAddress((void**)&xz,       g_xz);
    cudaGetSymbolAddress((void**)&xb,       g_xb);
    cudaGetSymbolAddress((void**)&xdbl,     g_xdbl);
    cudaGetSymbolAddress((void**)&y,        g_y);
    cudaGetSymbolAddress((void**)&wpatch,   g_wpatch);
    cudaGetSymbolAddress((void**)&win,      g_win);
    cudaGetSymbolAddress((void**)&wx,       g_wx);
    cudaGetSymbolAddress((void**)&wout,     g_wout);

    cudaFuncSetAttribute(gemm_mma,  cudaFuncAttributeMaxDynamicSharedMemorySize, 2*STAGE_BYTES);
    cudaFuncSetAttribute(gemm_wide, cudaFuncAttributeMaxDynamicSharedMemorySize, 3*WIDE_STAGE);
    cudaFuncSetAttribute(gemm_mma,  cudaFuncAttributePreferredSharedMemoryCarveout, 100);
    cudaFuncSetAttribute(gemm_wide, cudaFuncAttributePreferredSharedMemoryCarveout, 100);

    // pre-round GEMM weights to tf32
    round_tf32_kernel<<<512, 256>>>(patch_w, wpatch, D_MODEL*K_PATCH);
    round_tf32_kernel<<<2048, 256>>>(in_w,   win,    DEPTH*2*D_INNER*D_MODEL);
    round_tf32_kernel<<<512, 256>>>(xproj_w, wx,     DEPTH*XPROJ_N*D_INNER);
    round_tf32_kernel<<<1024, 256>>>(out_w,  wout,   DEPTH*D_MODEL*D_INNER);

    // patch embed -> residual (plain write)
    im2col_kernel<<<(ROWS*K_PATCH + 255)/256, 256>>>(x, xz);
    gemm_mma<<<dim3(3, ROWS/128), 256, 2*STAGE_BYTES>>>(xz, wpatch, residual,
                                                        ROWS, D_MODEL, K_PATCH, patch_b, 0,
                                                        K_PATCH, 0);

    for (int i = 0; i < DEPTH; i++) {
        ln_kernel<<<ROWS/8, 256>>>(residual, hn,
                                   norm_w + (size_t)i*D_MODEL, norm_b + (size_t)i*D_MODEL);
        gemm_wide<<<dim3(6, ROWS/128), 256, 3*WIDE_STAGE>>>(
            hn, win + (size_t)i*2*D_INNER*D_MODEL, xz, ROWS, 2*D_INNER, D_MODEL);
        conv_silu_kernel<<<dim3(B_SZ, 4), 384>>>(xz, conv_w + (size_t)i*D_INNER*D_CONV,
                                                 conv_b + (size_t)i*D_INNER, xb);
        gemm_mma<<<dim3(1, ROWS/128, 2), 256, 2*STAGE_BYTES>>>(
            xb, wx + (size_t)i*XPROJ_N*D_INNER, xdbl, ROWS, XPROJ_N, D_INNER/2, nullptr, 0,
            D_INNER, (size_t)ROWS*XPROJ_N);
        scan_kernel<<<dim3(D_INNER/128, B_SZ), 256>>>(
            xb, xdbl, xz, A_log + (size_t)i*D_INNER*D_STATE, D_skip + (size_t)i*D_INNER,
            dt_w + (size_t)i*D_INNER*DT_RANK, dt_b + (size_t)i*D_INNER, y);
        gemm_mma<<<dim3(3, ROWS/128), 256, 2*STAGE_BYTES>>>(
            y, wout + (size_t)i*D_MODEL*D_INNER, residual, ROWS, D_MODEL, D_INNER, nullptr, 1,
            D_INNER, 0);
    }

    final_kernel<<<B_SZ, 256>>>(residual, normf_w, normf_b, head_w, head_b, out);
}